// round 4
// baseline (speedup 1.0000x reference)
#include <cuda_runtime.h>
#include <math.h>

#define HIDDEN 2048
#define NUM_HEADS 16
#define HEAD_DIM 128
#define BLOCK_SIZE 64
#define NUM_SEQS 64
#define MAX_SEQ_LEN 2048
#define MAX_BLOCKS 32
#define NUM_BLOCKS_KV 2048
#define SCALE 0.08838834764831843f   // 1/sqrt(128)

#define KSPLIT 16
#define PART 8
#define PART_LEN 256   // MAX_SEQ_LEN / PART

// Scratch (device globals; no allocation allowed)
__device__ float g_q[NUM_SEQS * HIDDEN];                   // Q projection result
__device__ float g_attn[NUM_SEQS * HIDDEN];                // attention output
__device__ float g_part[KSPLIT * NUM_SEQS * HIDDEN];       // split-K partials
__device__ float g_pacc[NUM_SEQS * NUM_HEADS * PART * HEAD_DIM]; // attn partial accum
__device__ float2 g_pml[NUM_SEQS * NUM_HEADS * PART];      // attn partial (m, l)

__device__ __forceinline__ float4 ldcs4(const float* p) {
    return __ldcs((const float4*)p);
}

// packed fp32x2 helpers (exact fp32 semantics, 2 FMAs per instruction)
__device__ __forceinline__ unsigned long long pack2(float lo, float hi) {
    unsigned long long r;
    asm("mov.b64 %0, {%1, %2};" : "=l"(r) : "f"(lo), "f"(hi));
    return r;
}
__device__ __forceinline__ void unpack2(unsigned long long v, float& lo, float& hi) {
    asm("mov.b64 {%0, %1}, %2;" : "=f"(lo), "=f"(hi) : "l"(v));
}
__device__ __forceinline__ void ffma2(unsigned long long& d, unsigned long long a, unsigned long long b) {
    asm("fma.rn.f32x2 %0, %1, %2, %3;" : "=l"(d) : "l"(a), "l"(b), "l"(d));
}

// ---------------------------------------------------------------------------
// Split-K GEMM: P[ks] = A[64 x K-slice] @ B[K x N (ldb)]  (n-tile 64 wide)
// block: 256 threads, tile 64x64, BK=16, thread tile 4x4, split-K=16 over grid.y
// Inner product uses fma.rn.f32x2 (FFMA2) — 2x fp32 pipe throughput.
// ---------------------------------------------------------------------------
__global__ __launch_bounds__(256) void gemm_splitk(
    const float* __restrict__ A, const float* __restrict__ B,
    float* __restrict__ P, int K, int ldb, int N)
{
    const int KS = K / KSPLIT;              // 128
    const int k_base = blockIdx.y * KS;
    const int n0 = blockIdx.x * 64;

    __shared__ float As[64][17];            // padded: conflict-free reads
    __shared__ float Bs[16][64];

    const int tid = threadIdx.x;
    const int tx = tid & 15;   // N dir (x4)
    const int ty = tid >> 4;   // M dir (x4)

    const int a_row = tid >> 2;          // 0..63
    const int a_c4  = (tid & 3) * 4;     // 0,4,8,12
    const int b_row = tid >> 4;          // 0..15
    const int b_c4  = (tid & 15) * 4;    // 0..60

    unsigned long long acc2[4][2];
#pragma unroll
    for (int i = 0; i < 4; i++) { acc2[i][0] = 0ull; acc2[i][1] = 0ull; }

    float4 ra = *(const float4*)&A[a_row * K + k_base + a_c4];
    float4 rb = *(const float4*)&B[(size_t)(k_base + b_row) * ldb + n0 + b_c4];

    for (int k0 = k_base; k0 < k_base + KS; k0 += 16) {
        As[a_row][a_c4 + 0] = ra.x;
        As[a_row][a_c4 + 1] = ra.y;
        As[a_row][a_c4 + 2] = ra.z;
        As[a_row][a_c4 + 3] = ra.w;
        *(float4*)&Bs[b_row][b_c4] = rb;
        __syncthreads();

        if (k0 + 16 < k_base + KS) {
            int kn = k0 + 16;
            ra = *(const float4*)&A[a_row * K + kn + a_c4];
            rb = *(const float4*)&B[(size_t)(kn + b_row) * ldb + n0 + b_c4];
        }

#pragma unroll
        for (int kk = 0; kk < 16; kk++) {
            float4 b4 = *(const float4*)&Bs[kk][tx * 4];
            unsigned long long b01 = pack2(b4.x, b4.y);
            unsigned long long b23 = pack2(b4.z, b4.w);
#pragma unroll
            for (int i = 0; i < 4; i++) {
                float a = As[ty * 4 + i][kk];
                unsigned long long a2 = pack2(a, a);
                ffma2(acc2[i][0], a2, b01);
                ffma2(acc2[i][1], a2, b23);
            }
        }
        __syncthreads();
    }

    float* Pp = P + (size_t)blockIdx.y * 64 * N;
#pragma unroll
    for (int i = 0; i < 4; i++) {
        float4 v;
        unpack2(acc2[i][0], v.x, v.y);
        unpack2(acc2[i][1], v.z, v.w);
        *(float4*)&Pp[(ty * 4 + i) * N + n0 + tx * 4] = v;
    }
}

// reduce KSPLIT partials + bias (float4 vectorized; MLP=16)
__global__ __launch_bounds__(256) void reduceK(
    const float4* __restrict__ P, const float4* __restrict__ bias,
    float4* __restrict__ C, int N4, int total4)
{
    int i = blockIdx.x * blockDim.x + threadIdx.x;
    if (i < total4) {
        float4 v = bias[i & (N4 - 1)];
        float4 t[KSPLIT];
#pragma unroll
        for (int p = 0; p < KSPLIT; p++) t[p] = P[(size_t)p * total4 + i];
#pragma unroll
        for (int p = 0; p < KSPLIT; p++) {
            v.x += t[p].x; v.y += t[p].y; v.z += t[p].z; v.w += t[p].w;
        }
        C[i] = v;
    }
}

// ---------------------------------------------------------------------------
// Flash-decode partition kernel: block = (seq, head, partition), 256 threads
// ---------------------------------------------------------------------------
__global__ __launch_bounds__(256) void attn_part_kernel(
    const float* __restrict__ kv_cache,      // [2, NB, bs, h, d]
    const int* __restrict__ block_tables,    // [S, MAX_BLOCKS]
    const int* __restrict__ seq_lens,        // [S]
    const float* __restrict__ qbuf)          // [S, HIDDEN]
{
    const int s = blockIdx.x;
    const int h = blockIdx.y;
    const int p = blockIdx.z;
    const int tid = threadIdx.x;
    const int warp = tid >> 5;
    const int lane = tid & 31;

    const int L  = seq_lens[s];
    const int t0 = p * PART_LEN;
    const int Lp = min(L - t0, PART_LEN);    // may be <= 0

    const int pidx = (s * NUM_HEADS + h) * PART + p;
    float* pacc = g_pacc + (size_t)pidx * HEAD_DIM;

    if (Lp <= 0) {
        if (tid < HEAD_DIM) pacc[tid] = 0.f;
        if (tid == 0) g_pml[pidx] = make_float2(-INFINITY, 0.f);
        return;
    }

    __shared__ float q[HEAD_DIM];
    __shared__ float scores[PART_LEN];
    __shared__ float accbuf[8 * HEAD_DIM];
    __shared__ float red[8];
    __shared__ int   sbt[PART_LEN / BLOCK_SIZE];

    if (tid < HEAD_DIM) q[tid] = qbuf[s * HIDDEN + h * HEAD_DIM + tid];
    if (tid < PART_LEN / BLOCK_SIZE)
        sbt[tid] = block_tables[s * MAX_BLOCKS + (t0 >> 6) + tid];
    __syncthreads();

    const float4 qv = *(const float4*)&q[lane * 4];
    const float* kc = kv_cache;
    const float* vc = kv_cache + (size_t)NUM_BLOCKS_KV * BLOCK_SIZE * NUM_HEADS * HEAD_DIM;

    // Pass 1: scores (warp per token, stride 8 warps)
    float lmax = -INFINITY;
#pragma unroll 4
    for (int t = warp; t < Lp; t += 8) {
        int blk = sbt[t >> 6];
        const float* kr = kc + (((size_t)blk * BLOCK_SIZE + ((t0 + t) & 63)) * NUM_HEADS + h) * HEAD_DIM;
        float4 k4 = ldcs4(kr + lane * 4);
        float d = qv.x * k4.x + qv.y * k4.y + qv.z * k4.z + qv.w * k4.w;
#pragma unroll
        for (int o = 16; o; o >>= 1) d += __shfl_xor_sync(0xffffffffu, d, o);
        d *= SCALE;
        if (lane == 0) scores[t] = d;
        lmax = fmaxf(lmax, d);
    }
    if (lane == 0) red[warp] = lmax;
    __syncthreads();
    float gmax = red[0];
#pragma unroll
    for (int w = 1; w < 8; w++) gmax = fmaxf(gmax, red[w]);
    __syncthreads();

    // exp + sum (unnormalized)
    float lsum = 0.f;
    for (int t = tid; t < Lp; t += 256) {
        float e = __expf(scores[t] - gmax);
        scores[t] = e;
        lsum += e;
    }
#pragma unroll
    for (int o = 16; o; o >>= 1) lsum += __shfl_xor_sync(0xffffffffu, lsum, o);
    if (lane == 0) red[warp] = lsum;
    __syncthreads();

    // Pass 2: acc = sum_t w[t] * V[t]  (unnormalized)
    float4 acc = make_float4(0.f, 0.f, 0.f, 0.f);
#pragma unroll 4
    for (int t = warp; t < Lp; t += 8) {
        int blk = sbt[t >> 6];
        const float* vr = vc + (((size_t)blk * BLOCK_SIZE + ((t0 + t) & 63)) * NUM_HEADS + h) * HEAD_DIM;
        float4 v4 = ldcs4(vr + lane * 4);
        float w = scores[t];
        acc.x += w * v4.x;
        acc.y += w * v4.y;
        acc.z += w * v4.z;
        acc.w += w * v4.w;
    }
    ((float4*)accbuf)[warp * 32 + lane] = acc;   // [warp][128 dims]
    __syncthreads();

    if (tid < HEAD_DIM) {
        float tot = 0.f;
#pragma unroll
        for (int w = 0; w < 8; w++) tot += accbuf[w * HEAD_DIM + tid];
        pacc[tid] = tot;
    }
    if (tid == 0) {
        float ls = 0.f;
#pragma unroll
        for (int w = 0; w < 8; w++) ls += red[w];
        g_pml[pidx] = make_float2(gmax, ls);
    }
}

// Combine partitions: block per seq, warp per head, lane owns 4 dims (float4)
__global__ __launch_bounds__(512) void attn_combine_kernel(float* __restrict__ out)
{
    const int s = blockIdx.x;
    const int h = threadIdx.x >> 5;
    const int lane = threadIdx.x & 31;
    const int base = (s * NUM_HEADS + h) * PART;

    float2 ml[PART];
#pragma unroll
    for (int p = 0; p < PART; p++) ml[p] = g_pml[base + p];

    float m = ml[0].x;
#pragma unroll
    for (int p = 1; p < PART; p++) m = fmaxf(m, ml[p].x);

    float l = 0.f;
    float4 o = make_float4(0.f, 0.f, 0.f, 0.f);
#pragma unroll
    for (int p = 0; p < PART; p++) {
        float sc = __expf(ml[p].x - m);     // -inf -> 0
        l += ml[p].y * sc;
        float4 v = *(const float4*)&g_pacc[(size_t)(base + p) * HEAD_DIM + lane * 4];
        o.x += v.x * sc; o.y += v.y * sc; o.z += v.z * sc; o.w += v.w * sc;
    }
    float inv = 1.f / l;
    o.x *= inv; o.y *= inv; o.z *= inv; o.w *= inv;
    *(float4*)&out[s * HIDDEN + h * HEAD_DIM + lane * 4] = o;
}

// ---------------------------------------------------------------------------
extern "C" void kernel_launch(void* const* d_in, const int* in_sizes, int n_in,
                              void* d_out, int out_size)
{
    const float* hidden  = (const float*)d_in[0];
    const float* kvcache = (const float*)d_in[1];
    const float* W_attn  = (const float*)d_in[2];
    const float* b_attn  = (const float*)d_in[3];
    const float* W_proj  = (const float*)d_in[4];
    const float* b_proj  = (const float*)d_in[5];
    const int*   btab    = (const int*)d_in[6];
    const int*   slens   = (const int*)d_in[7];
    float* out = (float*)d_out;

    float *gq, *gattn, *gpart;
    cudaGetSymbolAddress((void**)&gq, g_q);
    cudaGetSymbolAddress((void**)&gattn, g_attn);
    cudaGetSymbolAddress((void**)&gpart, g_part);

    const int total = NUM_SEQS * HIDDEN;   // 131072
    const int total4 = total / 4;          // 32768
    const int N4 = HIDDEN / 4;             // 512

    // 1) Q projection only (first HIDDEN columns of W_attn), split-K=16
    gemm_splitk<<<dim3(HIDDEN / 64, KSPLIT), 256>>>(hidden, W_attn, gpart, HIDDEN, 3 * HIDDEN, HIDDEN);
    reduceK<<<(total4 + 255) / 256, 256>>>((const float4*)gpart, (const float4*)b_attn,
                                           (float4*)gq, N4, total4);

    // 2) paged attention: flash-decode split + combine
    attn_part_kernel<<<dim3(NUM_SEQS, NUM_HEADS, PART), 256>>>(kvcache, btab, slens, gq);
    attn_combine_kernel<<<NUM_SEQS, 512>>>(gattn);

    // 3) output projection, split-K=16
    gemm_splitk<<<dim3(HIDDEN / 64, KSPLIT), 256>>>(gattn, W_proj, gpart, HIDDEN, HIDDEN, HIDDEN);
    reduceK<<<(total4 + 255) / 256, 256>>>((const float4*)gpart, (const float4*)b_proj,
                                           (float4*)out, N4, total4);
}

// round 5
// speedup vs baseline: 1.0289x; 1.0289x over previous
#include <cuda_runtime.h>
#include <math.h>

#define HIDDEN 2048
#define NUM_HEADS 16
#define HEAD_DIM 128
#define BLOCK_SIZE 64
#define NUM_SEQS 64
#define MAX_SEQ_LEN 2048
#define MAX_BLOCKS 32
#define NUM_BLOCKS_KV 2048
#define SCALE 0.08838834764831843f   // 1/sqrt(128)

#define KSPLIT 16
#define PART 32            // one KV page (64 tokens) per partition

// Scratch (device globals; no allocation allowed)
__device__ float g_q[NUM_SEQS * HIDDEN];                   // Q projection result
__device__ float g_attn[NUM_SEQS * HIDDEN];                // attention output
__device__ float g_part[KSPLIT * NUM_SEQS * HIDDEN];       // split-K partials
__device__ float g_pacc[NUM_SEQS * NUM_HEADS * PART * HEAD_DIM]; // attn partial accum (16MB)
__device__ float2 g_pml[NUM_SEQS * NUM_HEADS * PART];      // attn partial (m, l)

__device__ __forceinline__ float4 ldcs4(const float* p) {
    return __ldcs((const float4*)p);
}

// ---------------------------------------------------------------------------
// Split-K GEMM (R3 version — plain FFMA, float4 tile loads)
// ---------------------------------------------------------------------------
__global__ __launch_bounds__(256) void gemm_splitk(
    const float* __restrict__ A, const float* __restrict__ B,
    float* __restrict__ P, int K, int ldb, int N)
{
    const int KS = K / KSPLIT;              // 128
    const int k_base = blockIdx.y * KS;
    const int n0 = blockIdx.x * 64;

    __shared__ float As[64][17];
    __shared__ float Bs[16][64];

    const int tid = threadIdx.x;
    const int tx = tid & 15;
    const int ty = tid >> 4;

    const int a_row = tid >> 2;
    const int a_c4  = (tid & 3) * 4;
    const int b_row = tid >> 4;
    const int b_c4  = (tid & 15) * 4;

    float acc[4][4];
#pragma unroll
    for (int i = 0; i < 4; i++)
#pragma unroll
        for (int j = 0; j < 4; j++) acc[i][j] = 0.f;

    float4 ra = *(const float4*)&A[a_row * K + k_base + a_c4];
    float4 rb = *(const float4*)&B[(size_t)(k_base + b_row) * ldb + n0 + b_c4];

    for (int k0 = k_base; k0 < k_base + KS; k0 += 16) {
        As[a_row][a_c4 + 0] = ra.x;
        As[a_row][a_c4 + 1] = ra.y;
        As[a_row][a_c4 + 2] = ra.z;
        As[a_row][a_c4 + 3] = ra.w;
        *(float4*)&Bs[b_row][b_c4] = rb;
        __syncthreads();

        if (k0 + 16 < k_base + KS) {
            int kn = k0 + 16;
            ra = *(const float4*)&A[a_row * K + kn + a_c4];
            rb = *(const float4*)&B[(size_t)(kn + b_row) * ldb + n0 + b_c4];
        }

#pragma unroll
        for (int kk = 0; kk < 16; kk++) {
            float4 b4 = *(const float4*)&Bs[kk][tx * 4];
            float a[4];
#pragma unroll
            for (int i = 0; i < 4; i++) a[i] = As[ty * 4 + i][kk];
#pragma unroll
            for (int i = 0; i < 4; i++) {
                acc[i][0] += a[i] * b4.x;
                acc[i][1] += a[i] * b4.y;
                acc[i][2] += a[i] * b4.z;
                acc[i][3] += a[i] * b4.w;
            }
        }
        __syncthreads();
    }

    float* Pp = P + (size_t)blockIdx.y * 64 * N;
#pragma unroll
    for (int i = 0; i < 4; i++) {
        float4 v = make_float4(acc[i][0], acc[i][1], acc[i][2], acc[i][3]);
        *(float4*)&Pp[(ty * 4 + i) * N + n0 + tx * 4] = v;
    }
}

// reduce KSPLIT partials + bias (float4 vectorized; MLP=16)
__global__ __launch_bounds__(256) void reduceK(
    const float4* __restrict__ P, const float4* __restrict__ bias,
    float4* __restrict__ C, int N4, int total4)
{
    int i = blockIdx.x * blockDim.x + threadIdx.x;
    if (i < total4) {
        float4 v = bias[i & (N4 - 1)];
        float4 t[KSPLIT];
#pragma unroll
        for (int p = 0; p < KSPLIT; p++) t[p] = P[(size_t)p * total4 + i];
#pragma unroll
        for (int p = 0; p < KSPLIT; p++) {
            v.x += t[p].x; v.y += t[p].y; v.z += t[p].z; v.w += t[p].w;
        }
        C[i] = v;
    }
}

// ---------------------------------------------------------------------------
// Page-streaming attention: block = (seq, page). All 16 heads per block.
// A token's KV row ([16 heads][128 dims] = 8KB) is read contiguously.
// ---------------------------------------------------------------------------
__global__ __launch_bounds__(256) void attn_part_kernel(
    const float* __restrict__ kv_cache,      // [2, NB, bs, h, d]
    const int* __restrict__ block_tables,    // [S, MAX_BLOCKS]
    const int* __restrict__ seq_lens,        // [S]
    const float* __restrict__ qbuf)          // [S, HIDDEN]
{
    const int s = blockIdx.x;
    const int p = blockIdx.y;
    const int tid = threadIdx.x;
    const int warp = tid >> 5;
    const int lane = tid & 31;

    const int L  = seq_lens[s];
    const int Lp = min(L - p * BLOCK_SIZE, BLOCK_SIZE);
    if (Lp <= 0) return;                     // combine never reads empty pages

    const int blk = __ldg(&block_tables[s * MAX_BLOCKS + p]);

    __shared__ float q[NUM_HEADS * HEAD_DIM];        // 8KB
    __shared__ float scores[NUM_HEADS * BLOCK_SIZE]; // 4KB  [h][t]
    __shared__ float red[8][NUM_HEADS];
    __shared__ float gmaxs[NUM_HEADS];
    __shared__ float lsums[NUM_HEADS];
    __shared__ float accbuf[8][8 * HEAD_DIM];        // 32KB

    // load q for all heads (2048 floats = 512 float4)
    ((float4*)q)[tid]       = ((const float4*)(qbuf + s * HIDDEN))[tid];
    ((float4*)q)[tid + 256] = ((const float4*)(qbuf + s * HIDDEN))[tid + 256];
    __syncthreads();

    const float* kpage = kv_cache + (size_t)blk * BLOCK_SIZE * HIDDEN;
    const float* vpage = kpage + (size_t)NUM_BLOCKS_KV * BLOCK_SIZE * HIDDEN;

    // ---- Pass 1: scores for all heads; warp = token (stride 8) ----
    float mymax = -INFINITY;      // lane h holds running max for head h (lane<16)
    for (int t = warp; t < Lp; t += 8) {
        const float* row = kpage + (size_t)t * HIDDEN + lane * 4;
        float sc_mine = 0.f;
#pragma unroll 4
        for (int h = 0; h < NUM_HEADS; h++) {
            float4 k4 = ldcs4(row + h * HEAD_DIM);
            float4 qh = *(const float4*)&q[h * HEAD_DIM + lane * 4];
            float d = qh.x * k4.x + qh.y * k4.y + qh.z * k4.z + qh.w * k4.w;
#pragma unroll
            for (int o = 16; o; o >>= 1) d += __shfl_xor_sync(0xffffffffu, d, o);
            d *= SCALE;
            if (lane == h) { mymax = fmaxf(mymax, d); sc_mine = d; }
        }
        if (lane < NUM_HEADS) scores[lane * BLOCK_SIZE + t] = sc_mine;
    }
    if (lane < NUM_HEADS) red[warp][lane] = mymax;
    __syncthreads();

    if (tid < NUM_HEADS) {
        float m = red[0][tid];
#pragma unroll
        for (int w = 1; w < 8; w++) m = fmaxf(m, red[w][tid]);
        gmaxs[tid] = m;
    }
    __syncthreads();

    // ---- exp + per-head sums: thread tid -> head tid>>4, 4 tokens ----
    {
        int h = tid >> 4, ii = tid & 15;
        float gm = gmaxs[h];
        float part = 0.f;
#pragma unroll
        for (int j = 0; j < 4; j++) {
            int t = ii * 4 + j;
            if (t < Lp) {
                float e = __expf(scores[h * BLOCK_SIZE + t] - gm);
                scores[h * BLOCK_SIZE + t] = e;
                part += e;
            }
        }
#pragma unroll
        for (int o = 8; o; o >>= 1) part += __shfl_xor_sync(0xffffffffu, part, o);
        if (ii == 0) lsums[h] = part;
    }
    __syncthreads();

    // ---- Pass 2: V accumulate; warp-pair = token, 8 heads per warp ----
    {
        const int g = warp & 1;          // head group (0: h0-7, 1: h8-15)
        float4 acc[8];
#pragma unroll
        for (int i = 0; i < 8; i++) acc[i] = make_float4(0.f, 0.f, 0.f, 0.f);

        for (int t = (warp >> 1); t < Lp; t += 4) {
            const float* row = vpage + (size_t)t * HIDDEN + g * (8 * HEAD_DIM) + lane * 4;
#pragma unroll
            for (int i = 0; i < 8; i++) {
                float w = scores[(g * 8 + i) * BLOCK_SIZE + t];
                float4 v4 = ldcs4(row + i * HEAD_DIM);
                acc[i].x += w * v4.x;
                acc[i].y += w * v4.y;
                acc[i].z += w * v4.z;
                acc[i].w += w * v4.w;
            }
        }
#pragma unroll
        for (int i = 0; i < 8; i++)
            *(float4*)&accbuf[warp][i * HEAD_DIM + lane * 4] = acc[i];
    }
    __syncthreads();

    // ---- final reduce (4 warp-partials per head) + write partials ----
#pragma unroll
    for (int e = 0; e < 8; e++) {
        int idx = tid + e * 256;          // 0..2047 = head*128 + dim
        int h = idx >> 7, d = idx & 127;
        int gg = h >> 3, i = h & 7;
        float sum = accbuf[gg][i * HEAD_DIM + d] + accbuf[gg + 2][i * HEAD_DIM + d]
                  + accbuf[gg + 4][i * HEAD_DIM + d] + accbuf[gg + 6][i * HEAD_DIM + d];
        g_pacc[((size_t)(s * NUM_HEADS + h) * PART + p) * HEAD_DIM + d] = sum;
    }
    if (tid < NUM_HEADS)
        g_pml[(s * NUM_HEADS + tid) * PART + p] = make_float2(gmaxs[tid], lsums[tid]);
}

// Combine: block per seq, warp per head, online softmax merge over valid pages
__global__ __launch_bounds__(512) void attn_combine_kernel(
    const int* __restrict__ seq_lens, float* __restrict__ out)
{
    const int s = blockIdx.x;
    const int h = threadIdx.x >> 5;
    const int lane = threadIdx.x & 31;
    const int base = (s * NUM_HEADS + h) * PART;
    const int nv = min((seq_lens[s] + BLOCK_SIZE - 1) >> 6, PART);

    float m = -INFINITY, l = 0.f;
    float4 o = make_float4(0.f, 0.f, 0.f, 0.f);
    for (int p = 0; p < nv; p++) {
        float2 ml = g_pml[base + p];
        float4 pa = *(const float4*)&g_pacc[(size_t)(base + p) * HEAD_DIM + lane * 4];
        if (ml.x > m) {
            float r = __expf(m - ml.x);
            l *= r; o.x *= r; o.y *= r; o.z *= r; o.w *= r;
            m = ml.x;
        }
        float sc = __expf(ml.x - m);
        l += ml.y * sc;
        o.x += pa.x * sc; o.y += pa.y * sc; o.z += pa.z * sc; o.w += pa.w * sc;
    }
    float inv = 1.f / l;
    o.x *= inv; o.y *= inv; o.z *= inv; o.w *= inv;
    *(float4*)&out[s * HIDDEN + h * HEAD_DIM + lane * 4] = o;
}

// ---------------------------------------------------------------------------
extern "C" void kernel_launch(void* const* d_in, const int* in_sizes, int n_in,
                              void* d_out, int out_size)
{
    const float* hidden  = (const float*)d_in[0];
    const float* kvcache = (const float*)d_in[1];
    const float* W_attn  = (const float*)d_in[2];
    const float* b_attn  = (const float*)d_in[3];
    const float* W_proj  = (const float*)d_in[4];
    const float* b_proj  = (const float*)d_in[5];
    const int*   btab    = (const int*)d_in[6];
    const int*   slens   = (const int*)d_in[7];
    float* out = (float*)d_out;

    float *gq, *gattn, *gpart;
    cudaGetSymbolAddress((void**)&gq, g_q);
    cudaGetSymbolAddress((void**)&gattn, g_attn);
    cudaGetSymbolAddress((void**)&gpart, g_part);

    const int total4 = NUM_SEQS * HIDDEN / 4;  // 32768
    const int N4 = HIDDEN / 4;                 // 512

    // 1) Q projection only (first HIDDEN columns of W_attn), split-K=16
    gemm_splitk<<<dim3(HIDDEN / 64, KSPLIT), 256>>>(hidden, W_attn, gpart, HIDDEN, 3 * HIDDEN, HIDDEN);
    reduceK<<<(total4 + 255) / 256, 256>>>((const float4*)gpart, (const float4*)b_attn,
                                           (float4*)gq, N4, total4);

    // 2) paged attention: page-streaming split + combine
    attn_part_kernel<<<dim3(NUM_SEQS, PART), 256>>>(kvcache, btab, slens, gq);
    attn_combine_kernel<<<NUM_SEQS, 512>>>(slens, gattn);

    // 3) output projection, split-K=16
    gemm_splitk<<<dim3(HIDDEN / 64, KSPLIT), 256>>>(gattn, W_proj, gpart, HIDDEN, HIDDEN, HIDDEN);
    reduceK<<<(total4 + 255) / 256, 256>>>((const float4*)gpart, (const float4*)b_proj,
                                           (float4*)out, N4, total4);
}

// round 6
// speedup vs baseline: 1.0412x; 1.0119x over previous
#include <cuda_runtime.h>
#include <math.h>

#define HIDDEN 2048
#define NUM_HEADS 16
#define HEAD_DIM 128
#define BLOCK_SIZE 64
#define NUM_SEQS 64
#define MAX_SEQ_LEN 2048
#define MAX_BLOCKS 32
#define NUM_BLOCKS_KV 2048
#define SCALE 0.08838834764831843f   // 1/sqrt(128)

#define KSPLIT 16
#define PART 32            // one KV page (64 tokens) per partition

// Scratch (device globals; no allocation allowed)
__device__ float g_q[NUM_SEQS * HIDDEN];                   // Q projection result
__device__ float g_attn[NUM_SEQS * HIDDEN];                // attention output
__device__ float g_part[KSPLIT * NUM_SEQS * HIDDEN];       // split-K partials
__device__ float g_pacc[NUM_SEQS * NUM_HEADS * PART * HEAD_DIM]; // attn partial accum (16MB)
__device__ float2 g_pml[NUM_SEQS * NUM_HEADS * PART];      // attn partial (m, l)

__device__ __forceinline__ float4 ldcs4(const float* p) {
    return __ldcs((const float4*)p);
}

// ---------------------------------------------------------------------------
// Split-K GEMM (plain FFMA, float4 tile loads)
// ---------------------------------------------------------------------------
__global__ __launch_bounds__(256) void gemm_splitk(
    const float* __restrict__ A, const float* __restrict__ B,
    float* __restrict__ P, int K, int ldb, int N)
{
    const int KS = K / KSPLIT;              // 128
    const int k_base = blockIdx.y * KS;
    const int n0 = blockIdx.x * 64;

    __shared__ float As[64][17];
    __shared__ float Bs[16][64];

    const int tid = threadIdx.x;
    const int tx = tid & 15;
    const int ty = tid >> 4;

    const int a_row = tid >> 2;
    const int a_c4  = (tid & 3) * 4;
    const int b_row = tid >> 4;
    const int b_c4  = (tid & 15) * 4;

    float acc[4][4];
#pragma unroll
    for (int i = 0; i < 4; i++)
#pragma unroll
        for (int j = 0; j < 4; j++) acc[i][j] = 0.f;

    float4 ra = *(const float4*)&A[a_row * K + k_base + a_c4];
    float4 rb = *(const float4*)&B[(size_t)(k_base + b_row) * ldb + n0 + b_c4];

    for (int k0 = k_base; k0 < k_base + KS; k0 += 16) {
        As[a_row][a_c4 + 0] = ra.x;
        As[a_row][a_c4 + 1] = ra.y;
        As[a_row][a_c4 + 2] = ra.z;
        As[a_row][a_c4 + 3] = ra.w;
        *(float4*)&Bs[b_row][b_c4] = rb;
        __syncthreads();

        if (k0 + 16 < k_base + KS) {
            int kn = k0 + 16;
            ra = *(const float4*)&A[a_row * K + kn + a_c4];
            rb = *(const float4*)&B[(size_t)(kn + b_row) * ldb + n0 + b_c4];
        }

#pragma unroll
        for (int kk = 0; kk < 16; kk++) {
            float4 b4 = *(const float4*)&Bs[kk][tx * 4];
            float a[4];
#pragma unroll
            for (int i = 0; i < 4; i++) a[i] = As[ty * 4 + i][kk];
#pragma unroll
            for (int i = 0; i < 4; i++) {
                acc[i][0] += a[i] * b4.x;
                acc[i][1] += a[i] * b4.y;
                acc[i][2] += a[i] * b4.z;
                acc[i][3] += a[i] * b4.w;
            }
        }
        __syncthreads();
    }

    float* Pp = P + (size_t)blockIdx.y * 64 * N;
#pragma unroll
    for (int i = 0; i < 4; i++) {
        float4 v = make_float4(acc[i][0], acc[i][1], acc[i][2], acc[i][3]);
        *(float4*)&Pp[(ty * 4 + i) * N + n0 + tx * 4] = v;
    }
}

// reduce KSPLIT partials + bias (float4 vectorized; MLP=16)
__global__ __launch_bounds__(256) void reduceK(
    const float4* __restrict__ P, const float4* __restrict__ bias,
    float4* __restrict__ C, int N4, int total4)
{
    int i = blockIdx.x * blockDim.x + threadIdx.x;
    if (i < total4) {
        float4 v = bias[i & (N4 - 1)];
        float4 t[KSPLIT];
#pragma unroll
        for (int p = 0; p < KSPLIT; p++) t[p] = P[(size_t)p * total4 + i];
#pragma unroll
        for (int p = 0; p < KSPLIT; p++) {
            v.x += t[p].x; v.y += t[p].y; v.z += t[p].z; v.w += t[p].w;
        }
        C[i] = v;
    }
}

// ---------------------------------------------------------------------------
// Page-streaming attention: block = (seq, page). All 16 heads per block.
// A token's KV row ([16 heads][128 dims] = 8KB) is read contiguously.
// ---------------------------------------------------------------------------
__global__ __launch_bounds__(256) void attn_part_kernel(
    const float* __restrict__ kv_cache,      // [2, NB, bs, h, d]
    const int* __restrict__ block_tables,    // [S, MAX_BLOCKS]
    const int* __restrict__ seq_lens,        // [S]
    const float* __restrict__ qbuf)          // [S, HIDDEN]
{
    const int s = blockIdx.x;
    const int p = blockIdx.y;
    const int tid = threadIdx.x;
    const int warp = tid >> 5;
    const int lane = tid & 31;

    const int L  = seq_lens[s];
    const int Lp = min(L - p * BLOCK_SIZE, BLOCK_SIZE);
    if (Lp <= 0) return;                     // combine never reads empty pages

    const int blk = __ldg(&block_tables[s * MAX_BLOCKS + p]);

    __shared__ float q[NUM_HEADS * HEAD_DIM];        // 8KB
    __shared__ float scores[NUM_HEADS * BLOCK_SIZE]; // 4KB  [h][t]
    __shared__ float red[8][NUM_HEADS];
    __shared__ float gmaxs[NUM_HEADS];
    __shared__ float lsums[NUM_HEADS];
    __shared__ float accbuf[8][8 * HEAD_DIM];        // 32KB

    // load q for all heads (2048 floats = 512 float4)
    ((float4*)q)[tid]       = ((const float4*)(qbuf + s * HIDDEN))[tid];
    ((float4*)q)[tid + 256] = ((const float4*)(qbuf + s * HIDDEN))[tid + 256];
    __syncthreads();

    const float* kpage = kv_cache + (size_t)blk * BLOCK_SIZE * HIDDEN;
    const float* vpage = kpage + (size_t)NUM_BLOCKS_KV * BLOCK_SIZE * HIDDEN;

    // ---- Pass 1: scores for all heads; warp = token (stride 8) ----
    float mymax = -INFINITY;      // lane h holds running max for head h (lane<16)
    for (int t = warp; t < Lp; t += 8) {
        const float* row = kpage + (size_t)t * HIDDEN + lane * 4;
        float sc_mine = 0.f;
#pragma unroll 4
        for (int h = 0; h < NUM_HEADS; h++) {
            float4 k4 = ldcs4(row + h * HEAD_DIM);
            float4 qh = *(const float4*)&q[h * HEAD_DIM + lane * 4];
            float d = qh.x * k4.x + qh.y * k4.y + qh.z * k4.z + qh.w * k4.w;
#pragma unroll
            for (int o = 16; o; o >>= 1) d += __shfl_xor_sync(0xffffffffu, d, o);
            d *= SCALE;
            if (lane == h) { mymax = fmaxf(mymax, d); sc_mine = d; }
        }
        if (lane < NUM_HEADS) scores[lane * BLOCK_SIZE + t] = sc_mine;
    }
    if (lane < NUM_HEADS) red[warp][lane] = mymax;
    __syncthreads();

    if (tid < NUM_HEADS) {
        float m = red[0][tid];
#pragma unroll
        for (int w = 1; w < 8; w++) m = fmaxf(m, red[w][tid]);
        gmaxs[tid] = m;
    }
    __syncthreads();

    // ---- exp + per-head sums: thread tid -> head tid>>4, 4 tokens ----
    {
        int h = tid >> 4, ii = tid & 15;
        float gm = gmaxs[h];
        float part = 0.f;
#pragma unroll
        for (int j = 0; j < 4; j++) {
            int t = ii * 4 + j;
            if (t < Lp) {
                float e = __expf(scores[h * BLOCK_SIZE + t] - gm);
                scores[h * BLOCK_SIZE + t] = e;
                part += e;
            }
        }
#pragma unroll
        for (int o = 8; o; o >>= 1) part += __shfl_xor_sync(0xffffffffu, part, o);
        if (ii == 0) lsums[h] = part;
    }
    __syncthreads();

    // ---- Pass 2: V accumulate; warp-pair = token, 8 heads per warp ----
    {
        const int g = warp & 1;          // head group (0: h0-7, 1: h8-15)
        float4 acc[8];
#pragma unroll
        for (int i = 0; i < 8; i++) acc[i] = make_float4(0.f, 0.f, 0.f, 0.f);

        for (int t = (warp >> 1); t < Lp; t += 4) {
            const float* row = vpage + (size_t)t * HIDDEN + g * (8 * HEAD_DIM) + lane * 4;
#pragma unroll
            for (int i = 0; i < 8; i++) {
                float w = scores[(g * 8 + i) * BLOCK_SIZE + t];
                float4 v4 = ldcs4(row + i * HEAD_DIM);
                acc[i].x += w * v4.x;
                acc[i].y += w * v4.y;
                acc[i].z += w * v4.z;
                acc[i].w += w * v4.w;
            }
        }
#pragma unroll
        for (int i = 0; i < 8; i++)
            *(float4*)&accbuf[warp][i * HEAD_DIM + lane * 4] = acc[i];
    }
    __syncthreads();

    // ---- final reduce (4 warp-partials per head) + write partials ----
#pragma unroll
    for (int e = 0; e < 8; e++) {
        int idx = tid + e * 256;          // 0..2047 = head*128 + dim
        int h = idx >> 7, d = idx & 127;
        int gg = h >> 3, i = h & 7;
        float sum = accbuf[gg][i * HEAD_DIM + d] + accbuf[gg + 2][i * HEAD_DIM + d]
                  + accbuf[gg + 4][i * HEAD_DIM + d] + accbuf[gg + 6][i * HEAD_DIM + d];
        g_pacc[((size_t)(s * NUM_HEADS + h) * PART + p) * HEAD_DIM + d] = sum;
    }
    if (tid < NUM_HEADS)
        g_pml[(s * NUM_HEADS + tid) * PART + p] = make_float2(gmaxs[tid], lsums[tid]);
}

// ---------------------------------------------------------------------------
// Combine: block = (seq, head), 256 threads. 8 warps each online-merge pages
// p = warp, warp+8, ... (<=4 serial steps), then 128-thread smem merge of 8.
// ---------------------------------------------------------------------------
__global__ __launch_bounds__(256) void attn_combine_kernel(
    const int* __restrict__ seq_lens, float* __restrict__ out)
{
    const int s = blockIdx.x;
    const int h = blockIdx.y;
    const int warp = threadIdx.x >> 5;
    const int lane = threadIdx.x & 31;
    const int base = (s * NUM_HEADS + h) * PART;
    const int nv = min((__ldg(&seq_lens[s]) + BLOCK_SIZE - 1) >> 6, PART);

    __shared__ float m8[8], l8[8];
    __shared__ float obuf[8][HEAD_DIM];

    float m = -INFINITY, l = 0.f;
    float4 o = make_float4(0.f, 0.f, 0.f, 0.f);
    for (int p = warp; p < nv; p += 8) {
        float2 ml = g_pml[base + p];
        float4 pa = *(const float4*)&g_pacc[(size_t)(base + p) * HEAD_DIM + lane * 4];
        if (ml.x > m) {
            float r = __expf(m - ml.x);
            l *= r; o.x *= r; o.y *= r; o.z *= r; o.w *= r;
            m = ml.x;
        }
        float sc = __expf(ml.x - m);
        l += ml.y * sc;
        o.x += pa.x * sc; o.y += pa.y * sc; o.z += pa.z * sc; o.w += pa.w * sc;
    }
    *(float4*)&obuf[warp][lane * 4] = o;
    if (lane == 0) { m8[warp] = m; l8[warp] = l; }
    __syncthreads();

    if (threadIdx.x < HEAD_DIM) {
        int d = threadIdx.x;
        float M = m8[0];
#pragma unroll
        for (int w = 1; w < 8; w++) M = fmaxf(M, m8[w]);
        float L = 0.f, O = 0.f;
#pragma unroll
        for (int w = 0; w < 8; w++) {
            float sc = (m8[w] == -INFINITY) ? 0.f : __expf(m8[w] - M);
            L += l8[w] * sc;
            O += obuf[w][d] * sc;
        }
        out[s * HIDDEN + h * HEAD_DIM + d] = O / L;
    }
}

// ---------------------------------------------------------------------------
extern "C" void kernel_launch(void* const* d_in, const int* in_sizes, int n_in,
                              void* d_out, int out_size)
{
    const float* hidden  = (const float*)d_in[0];
    const float* kvcache = (const float*)d_in[1];
    const float* W_attn  = (const float*)d_in[2];
    const float* b_attn  = (const float*)d_in[3];
    const float* W_proj  = (const float*)d_in[4];
    const float* b_proj  = (const float*)d_in[5];
    const int*   btab    = (const int*)d_in[6];
    const int*   slens   = (const int*)d_in[7];
    float* out = (float*)d_out;

    float *gq, *gattn, *gpart;
    cudaGetSymbolAddress((void**)&gq, g_q);
    cudaGetSymbolAddress((void**)&gattn, g_attn);
    cudaGetSymbolAddress((void**)&gpart, g_part);

    const int total4 = NUM_SEQS * HIDDEN / 4;  // 32768
    const int N4 = HIDDEN / 4;                 // 512

    // 1) Q projection only (first HIDDEN columns of W_attn), split-K=16
    gemm_splitk<<<dim3(HIDDEN / 64, KSPLIT), 256>>>(hidden, W_attn, gpart, HIDDEN, 3 * HIDDEN, HIDDEN);
    reduceK<<<(total4 + 255) / 256, 256>>>((const float4*)gpart, (const float4*)b_attn,
                                           (float4*)gq, N4, total4);

    // 2) paged attention: page-streaming split + combine
    attn_part_kernel<<<dim3(NUM_SEQS, PART), 256>>>(kvcache, btab, slens, gq);
    attn_combine_kernel<<<dim3(NUM_SEQS, NUM_HEADS), 256>>>(slens, gattn);

    // 3) output projection, split-K=16
    gemm_splitk<<<dim3(HIDDEN / 64, KSPLIT), 256>>>(gattn, W_proj, gpart, HIDDEN, HIDDEN, HIDDEN);
    reduceK<<<(total4 + 255) / 256, 256>>>((const float4*)gpart, (const float4*)b_proj,
                                           (float4*)out, N4, total4);
}